// round 2
// baseline (speedup 1.0000x reference)
#include <cuda_runtime.h>
#include <cuda_bf16.h>
#include <math.h>

#define NN    50000
#define EE    800000
#define ETOT  (EE + NN)     // edges + self loops
#define HH    4
#define CC    32
#define HC    128
#define NHID  512
#define NOUT  768
#define GG    256

// ---------------- scratch (device globals; no allocation allowed) ----------
__device__ float g_h [NN * HC];     // h = x @ W
__device__ float g_sk[NN * HC];     // skip = x @ skW
__device__ float g_x [NN * HC];     // layer output / next input
__device__ float g_esrc[NN * HH];
__device__ float g_edst[NN * HH];
__device__ int   g_deg[NN];
__device__ int   g_cnt[NN];
__device__ int   g_off[NN + 1];
__device__ int   g_srcidx[ETOT];
__device__ int   g_bsum[64];
__device__ int   g_bpre[64];
__device__ float g_pool[GG * HC];
__device__ float g_hid [GG * NHID];
__device__ int   g_is64;

// ---------------- dtype detection for edge_index / batch -------------------
__global__ void detect_k(const unsigned* __restrict__ w) {
    int all0 = 1;
    for (int i = 0; i < 256; ++i)
        if (w[2 * i + 1] != 0u) { all0 = 0; break; }
    g_is64 = all0;
}

__device__ __forceinline__ int fetch_idx(const void* p, long i, int is64) {
    if (is64) return (int)((const long long*)p)[i];
    return ((const int*)p)[i];
}

// ---------------- init ------------------------------------------------------
__global__ void init_k() {
    int i = blockIdx.x * blockDim.x + threadIdx.x;
    if (i < NN) { g_deg[i] = 1; g_cnt[i] = 0; }
    if (i < GG * HC) g_pool[i] = 0.0f;
}

__global__ void hist_k(const void* __restrict__ ei) {
    int e = blockIdx.x * blockDim.x + threadIdx.x;
    if (e >= EE) return;
    int is64 = g_is64;
    int d = fetch_idx(ei, (long)EE + e, is64);
    atomicAdd(&g_deg[d], 1);
}

// two-level inclusive scan over g_deg -> exclusive offsets in g_off
__global__ void scan1_k() {
    __shared__ int sh[1024];
    int t = threadIdx.x;
    int i = blockIdx.x * 1024 + t;
    int v = (i < NN) ? g_deg[i] : 0;
    sh[t] = v;
    for (int off = 1; off < 1024; off <<= 1) {
        __syncthreads();
        int x = (t >= off) ? sh[t - off] : 0;
        __syncthreads();
        sh[t] += x;
    }
    __syncthreads();
    if (i < NN) g_off[i] = sh[t];
    if (t == 1023) g_bsum[blockIdx.x] = sh[1023];
}

__global__ void scan2_k(int nblk) {
    if (threadIdx.x == 0) {
        int acc = 0;
        for (int b = 0; b < nblk; ++b) { g_bpre[b] = acc; acc += g_bsum[b]; }
    }
}

__global__ void scan3_k() {
    int t = threadIdx.x;
    int i = blockIdx.x * 1024 + t;
    if (i < NN) g_off[i] = g_off[i] + g_bpre[blockIdx.x] - g_deg[i];
    if (i == 0) g_off[NN] = ETOT;
}

__global__ void scatter_k(const void* __restrict__ ei) {
    long idx = (long)blockIdx.x * blockDim.x + threadIdx.x;
    if (idx >= ETOT) return;
    int is64 = g_is64;
    int s, d;
    if (idx < EE) {
        s = fetch_idx(ei, idx, is64);
        d = fetch_idx(ei, (long)EE + idx, is64);
    } else {
        s = d = (int)(idx - EE);
    }
    int p = g_off[d] + atomicAdd(&g_cnt[d], 1);
    g_srcidx[p] = s;
}

// ---------------- fused dual SGEMM: 128x128 tile, 8x8 microtile -------------
// blockIdx.y == 0: C0 = A @ B0 ; blockIdx.y == 1: C1 = A @ B1
// Double-buffered smem, one barrier per K-step, rows padded to 132 floats.
__global__ __launch_bounds__(256, 2)
void gemm128_k(const float* __restrict__ A,
               const float* __restrict__ B0, const float* __restrict__ B1,
               float* __restrict__ C0, float* __restrict__ C1, int M) {
    const float* B = blockIdx.y ? B1 : B0;
    float*       C = blockIdx.y ? C1 : C0;
    __shared__ float As[2][8][132];
    __shared__ float Bs[2][8][132];
    int tid = threadIdx.x;
    int m0 = blockIdx.x * 128;
    int tm = (tid >> 4) * 8;      // row group
    int tn = (tid & 15) * 8;      // col group
    int arow = tid >> 1;          // 0..127
    int akp  = (tid & 1) * 4;     // 0 or 4
    int bk   = tid >> 5;          // 0..7
    int bc   = (tid & 31) * 4;    // 0..124

    float c[8][8] = {};
    float4 av, bv;
    {
        int row = m0 + arow;
        av = (row < M) ? *(const float4*)&A[(size_t)row * 128 + akp]
                       : make_float4(0.f, 0.f, 0.f, 0.f);
        bv = *(const float4*)&B[(size_t)bk * 128 + bc];
        As[0][akp + 0][arow] = av.x; As[0][akp + 1][arow] = av.y;
        As[0][akp + 2][arow] = av.z; As[0][akp + 3][arow] = av.w;
        *(float4*)&Bs[0][bk][bc] = bv;
    }
    __syncthreads();
    int cur = 0;
    for (int k0 = 0; k0 < 128; k0 += 8) {
        if (k0 + 8 < 128) {
            int row = m0 + arow;
            av = (row < M) ? *(const float4*)&A[(size_t)row * 128 + k0 + 8 + akp]
                           : make_float4(0.f, 0.f, 0.f, 0.f);
            bv = *(const float4*)&B[(size_t)(k0 + 8 + bk) * 128 + bc];
        }
#pragma unroll
        for (int kk = 0; kk < 8; ++kk) {
            float a[8], b[8];
            *(float4*)&a[0] = *(const float4*)&As[cur][kk][tm];
            *(float4*)&a[4] = *(const float4*)&As[cur][kk][tm + 4];
            *(float4*)&b[0] = *(const float4*)&Bs[cur][kk][tn];
            *(float4*)&b[4] = *(const float4*)&Bs[cur][kk][tn + 4];
#pragma unroll
            for (int i = 0; i < 8; ++i)
#pragma unroll
                for (int j = 0; j < 8; ++j)
                    c[i][j] += a[i] * b[j];
        }
        if (k0 + 8 < 128) {
            int nxt = cur ^ 1;
            As[nxt][akp + 0][arow] = av.x; As[nxt][akp + 1][arow] = av.y;
            As[nxt][akp + 2][arow] = av.z; As[nxt][akp + 3][arow] = av.w;
            *(float4*)&Bs[nxt][bk][bc] = bv;
            __syncthreads();
            cur = nxt;
        }
    }
#pragma unroll
    for (int i = 0; i < 8; ++i) {
        int row = m0 + tm + i;
        if (row < M) {
            *(float4*)&C[(size_t)row * 128 + tn] =
                make_float4(c[i][0], c[i][1], c[i][2], c[i][3]);
            *(float4*)&C[(size_t)row * 128 + tn + 4] =
                make_float4(c[i][4], c[i][5], c[i][6], c[i][7]);
        }
    }
}

// ---------------- attention scores ------------------------------------------
__global__ void attn_k(const float* __restrict__ as_, const float* __restrict__ ad_) {
    int n = blockIdx.x * blockDim.x + threadIdx.x;
    if (n >= NN) return;
    const float* hr = &g_h[(size_t)n * 128];
#pragma unroll
    for (int h = 0; h < HH; ++h) {
        float s1 = 0.f, s2 = 0.f;
#pragma unroll
        for (int c = 0; c < CC; c += 4) {
            float4 hv = *(const float4*)&hr[h * CC + c];
            float4 a1 = *(const float4*)&as_[h * CC + c];
            float4 a2 = *(const float4*)&ad_[h * CC + c];
            s1 += hv.x * a1.x + hv.y * a1.y + hv.z * a1.z + hv.w * a1.w;
            s2 += hv.x * a2.x + hv.y * a2.y + hv.z * a2.z + hv.w * a2.w;
        }
        g_esrc[n * HH + h] = s1;
        g_edst[n * HH + h] = s2;
    }
}

// ---------------- warp-per-node online-softmax aggregation ------------------
__global__ void aggregate_k(const float* __restrict__ bias,
                            const float* __restrict__ skb) {
    int warp = (blockIdx.x * blockDim.x + threadIdx.x) >> 5;
    int lane = threadIdx.x & 31;
    if (warp >= NN) return;
    int n = warp;
    int head = lane >> 3;
    float ed = g_edst[n * HH + head];
    int j0 = g_off[n], j1 = g_off[n + 1];
    float m = -1e30f, z = 0.f;
    float4 acc = make_float4(0.f, 0.f, 0.f, 0.f);
    for (int j = j0; j < j1; ++j) {
        int s = g_srcidx[j];
        float e = g_esrc[s * HH + head] + ed;
        e = (e > 0.f) ? e : 0.2f * e;
        float nm = fmaxf(m, e);
        float sc = __expf(m - nm);
        float w  = __expf(e - nm);
        float4 hv = *(const float4*)&g_h[(size_t)s * 128 + lane * 4];
        acc.x = acc.x * sc + w * hv.x;
        acc.y = acc.y * sc + w * hv.y;
        acc.z = acc.z * sc + w * hv.z;
        acc.w = acc.w * sc + w * hv.w;
        z = z * sc + w;
        m = nm;
    }
    float inv = 1.f / z;
    float4 sk = *(const float4*)&g_sk[(size_t)n * 128 + lane * 4];
    float4 bb = *(const float4*)&bias[lane * 4];
    float4 sb = *(const float4*)&skb[lane * 4];
    float4 o;
    o.x = fmaxf(0.f, acc.x * inv + bb.x + sk.x + sb.x);
    o.y = fmaxf(0.f, acc.y * inv + bb.y + sk.y + sb.y);
    o.z = fmaxf(0.f, acc.z * inv + bb.z + sk.z + sb.z);
    o.w = fmaxf(0.f, acc.w * inv + bb.w + sk.w + sb.w);
    *(float4*)&g_x[(size_t)n * 128 + lane * 4] = o;
}

// ---------------- global max pool --------------------------------------------
__global__ void pool_k(const void* __restrict__ batch) {
    int n = blockIdx.x;
    int t = threadIdx.x;
    int is64 = g_is64;
    int g = fetch_idx(batch, n, is64);
    float v = g_x[(size_t)n * 128 + t];
    atomicMax((int*)&g_pool[g * 128 + t], __float_as_int(v));
}

// ---------------- MLP --------------------------------------------------------
__global__ void mlp1_k(const float* __restrict__ w, const float* __restrict__ b) {
    __shared__ float sp[HC];
    int g = blockIdx.x, t = threadIdx.x;
    if (t < HC) sp[t] = g_pool[g * HC + t];
    __syncthreads();
    float s = b[t];
#pragma unroll 8
    for (int k = 0; k < HC; ++k) s += sp[k] * w[(size_t)k * NHID + t];
    g_hid[(size_t)g * NHID + t] = fmaxf(s, 0.f);
}

__global__ void mlp2_k(const float* __restrict__ w, const float* __restrict__ b,
                       float* __restrict__ out) {
    __shared__ float sp[NHID];
    int g = blockIdx.x, t = threadIdx.x;
    if (t < NHID) sp[t] = g_hid[(size_t)g * NHID + t];
    __syncthreads();
    float s = b[t];
#pragma unroll 8
    for (int k = 0; k < NHID; ++k) s += sp[k] * w[(size_t)k * NOUT + t];
    out[(size_t)g * NOUT + t] = s;
}

// ---------------- launch ------------------------------------------------------
extern "C" void kernel_launch(void* const* d_in, const int* in_sizes, int n_in,
                              void* d_out, int out_size) {
    const float* x     = (const float*)d_in[0];
    const void*  ei    = d_in[1];
    const void*  batch = d_in[2];
    const float* w[3]   = {(const float*)d_in[3],  (const float*)d_in[9],  (const float*)d_in[15]};
    const float* as_[3] = {(const float*)d_in[4],  (const float*)d_in[10], (const float*)d_in[16]};
    const float* ad_[3] = {(const float*)d_in[5],  (const float*)d_in[11], (const float*)d_in[17]};
    const float* b[3]   = {(const float*)d_in[6],  (const float*)d_in[12], (const float*)d_in[18]};
    const float* skw[3] = {(const float*)d_in[7],  (const float*)d_in[13], (const float*)d_in[19]};
    const float* skb[3] = {(const float*)d_in[8],  (const float*)d_in[14], (const float*)d_in[20]};
    const float* m1w = (const float*)d_in[21];
    const float* m1b = (const float*)d_in[22];
    const float* m2w = (const float*)d_in[23];
    const float* m2b = (const float*)d_in[24];
    float* out = (float*)d_out;

    float *ph, *psk, *px;
    cudaGetSymbolAddress((void**)&ph,  g_h);
    cudaGetSymbolAddress((void**)&psk, g_sk);
    cudaGetSymbolAddress((void**)&px,  g_x);

    const int SCAN_BLOCKS = (NN + 1023) / 1024;   // 49

    detect_k<<<1, 1>>>((const unsigned*)ei);
    init_k<<<(NN + 255) / 256, 256>>>();
    hist_k<<<(EE + 255) / 256, 256>>>(ei);
    scan1_k<<<SCAN_BLOCKS, 1024>>>();
    scan2_k<<<1, 32>>>(SCAN_BLOCKS);
    scan3_k<<<SCAN_BLOCKS, 1024>>>();
    scatter_k<<<(ETOT + 255) / 256, 256>>>(ei);

    dim3 ggrid((NN + 127) / 128, 2);
    for (int L = 0; L < 3; ++L) {
        const float* A = (L == 0) ? x : px;
        gemm128_k<<<ggrid, 256>>>(A, w[L], skw[L], ph, psk, NN);
        attn_k<<<(NN + 127) / 128, 128>>>(as_[L], ad_[L]);
        aggregate_k<<<(NN * 32 + 255) / 256, 256>>>(b[L], skb[L]);
    }

    pool_k<<<NN, 128>>>(batch);
    mlp1_k<<<GG, NHID>>>(m1w, m1b);
    mlp2_k<<<GG, NOUT>>>(m2w, m2b, out);
}

// round 4
// speedup vs baseline: 1.3744x; 1.3744x over previous
#include <cuda_runtime.h>
#include <cuda_bf16.h>
#include <math.h>
#include <stdint.h>

#define NN    50000
#define EE    800000
#define ETOT  (EE + NN)     // edges + self loops
#define HH    4
#define CC    32
#define HC    128
#define NHID  512
#define NOUT  768
#define GG    256

#define SPAD  136           // smem row stride (bf16 elems), conflict-free

// ---------------- scratch (device globals; no allocation allowed) ----------
__device__ float g_h [NN * HC];     // h = x @ W
__device__ float g_sk[NN * HC];     // skip = x @ skW
__device__ float g_x [NN * HC];     // layer output / next input
__device__ float g_esrc[NN * HH];
__device__ float g_edst[NN * HH];
__device__ int   g_deg[NN];
__device__ int   g_cnt[NN];
__device__ int   g_off[NN + 1];
__device__ int   g_srcidx[ETOT];
__device__ int   g_bsum[64];
__device__ int   g_bpre[64];
__device__ float g_pool[GG * HC];
__device__ float g_hid [GG * NHID];
__device__ int   g_is64;
// transposed + split weights: index 2L = W, 2L+1 = skW; layout [n][k]
__device__ __nv_bfloat16 g_wthi[6 * 128 * 128];
__device__ __nv_bfloat16 g_wtlo[6 * 128 * 128];

// ---------------- dtype detection for edge_index / batch -------------------
__global__ void detect_k(const unsigned* __restrict__ w) {
    int all0 = 1;
    for (int i = 0; i < 256; ++i)
        if (w[2 * i + 1] != 0u) { all0 = 0; break; }
    g_is64 = all0;
}

__device__ __forceinline__ int fetch_idx(const void* p, long i, int is64) {
    if (is64) return (int)((const long long*)p)[i];
    return ((const int*)p)[i];
}

// ---------------- init ------------------------------------------------------
__global__ void init_k() {
    int i = blockIdx.x * blockDim.x + threadIdx.x;
    if (i < NN) { g_deg[i] = 1; g_cnt[i] = 0; }
    if (i < GG * HC) g_pool[i] = 0.0f;
}

__global__ void hist_k(const void* __restrict__ ei) {
    int e = blockIdx.x * blockDim.x + threadIdx.x;
    if (e >= EE) return;
    int is64 = g_is64;
    int d = fetch_idx(ei, (long)EE + e, is64);
    atomicAdd(&g_deg[d], 1);
}

__global__ void scan1_k() {
    __shared__ int sh[1024];
    int t = threadIdx.x;
    int i = blockIdx.x * 1024 + t;
    int v = (i < NN) ? g_deg[i] : 0;
    sh[t] = v;
    for (int off = 1; off < 1024; off <<= 1) {
        __syncthreads();
        int x = (t >= off) ? sh[t - off] : 0;
        __syncthreads();
        sh[t] += x;
    }
    __syncthreads();
    if (i < NN) g_off[i] = sh[t];
    if (t == 1023) g_bsum[blockIdx.x] = sh[1023];
}

__global__ void scan2_k(int nblk) {
    if (threadIdx.x == 0) {
        int acc = 0;
        for (int b = 0; b < nblk; ++b) { g_bpre[b] = acc; acc += g_bsum[b]; }
    }
}

__global__ void scan3_k() {
    int t = threadIdx.x;
    int i = blockIdx.x * 1024 + t;
    if (i < NN) g_off[i] = g_off[i] + g_bpre[blockIdx.x] - g_deg[i];
    if (i == 0) g_off[NN] = ETOT;
}

__global__ void scatter_k(const void* __restrict__ ei) {
    long idx = (long)blockIdx.x * blockDim.x + threadIdx.x;
    if (idx >= ETOT) return;
    int is64 = g_is64;
    int s, d;
    if (idx < EE) {
        s = fetch_idx(ei, idx, is64);
        d = fetch_idx(ei, (long)EE + idx, is64);
    } else {
        s = d = (int)(idx - EE);
    }
    int p = g_off[d] + atomicAdd(&g_cnt[d], 1);
    g_srcidx[p] = s;
}

// ---------------- weight prep: transpose + split into bf16 hi/lo ------------
__global__ void prep_w_k(const float* w0, const float* w1, const float* w2,
                         const float* w3, const float* w4, const float* w5) {
    const float* src[6] = {w0, w1, w2, w3, w4, w5};
    int b = blockIdx.x;
    const float* W = src[b];
    __nv_bfloat16* hi = g_wthi + b * 16384;
    __nv_bfloat16* lo = g_wtlo + b * 16384;
    for (int idx = threadIdx.x; idx < 16384; idx += blockDim.x) {
        int n = idx >> 7, k = idx & 127;
        float x = W[k * 128 + n];            // transpose: [n][k] <- W[k][n]
        __nv_bfloat16 h = __float2bfloat16(x);
        float r = x - __bfloat162float(h);
        hi[idx] = h;
        lo[idx] = __float2bfloat16(r);
    }
}

// ---------------- split-bf16 mma.sync GEMM ----------------------------------
// C[M,128] = A[M,128] @ B[128,128], emulated fp32 via 3 bf16 MMA terms.
// blockIdx.y selects (B0,C0) vs (B1,C1). 8 warps, each owns 32x64 of C.
__device__ __forceinline__ void mma16816(float* c, const uint32_t* a, const uint32_t* b) {
    asm volatile(
        "mma.sync.aligned.m16n8k16.row.col.f32.bf16.bf16.f32 "
        "{%0,%1,%2,%3}, {%4,%5,%6,%7}, {%8,%9}, {%0,%1,%2,%3};"
        : "+f"(c[0]), "+f"(c[1]), "+f"(c[2]), "+f"(c[3])
        : "r"(a[0]), "r"(a[1]), "r"(a[2]), "r"(a[3]), "r"(b[0]), "r"(b[1]));
}

__global__ __launch_bounds__(256, 1)
void gemm_mma_k(const float* __restrict__ A,
                const __nv_bfloat16* __restrict__ B0hi, const __nv_bfloat16* __restrict__ B0lo,
                const __nv_bfloat16* __restrict__ B1hi, const __nv_bfloat16* __restrict__ B1lo,
                float* __restrict__ C0, float* __restrict__ C1, int M) {
    extern __shared__ __nv_bfloat16 sm[];
    __nv_bfloat16* sAhi = sm;
    __nv_bfloat16* sAlo = sm + 128 * SPAD;
    __nv_bfloat16* sBhi = sm + 2 * 128 * SPAD;
    __nv_bfloat16* sBlo = sm + 3 * 128 * SPAD;

    const __nv_bfloat16* Bhi = blockIdx.y ? B1hi : B0hi;
    const __nv_bfloat16* Blo = blockIdx.y ? B1lo : B0lo;
    float*               C   = blockIdx.y ? C1  : C0;

    int tid = threadIdx.x;
    int m0 = blockIdx.x * 128;

    // ---- stage A (fp32 -> bf16 hi/lo) and B (bf16) into padded smem ----
    union P8 { __nv_bfloat16 b[8]; uint4 u; };
#pragma unroll
    for (int it = 0; it < 8; ++it) {
        int idx = tid + it * 256;          // 0..2047, each = 8 elems
        int row = idx >> 4;
        int col = (idx & 15) * 8;
        float4 a0 = make_float4(0.f, 0.f, 0.f, 0.f), a1 = a0;
        if (m0 + row < M) {
            a0 = *(const float4*)&A[(size_t)(m0 + row) * 128 + col];
            a1 = *(const float4*)&A[(size_t)(m0 + row) * 128 + col + 4];
        }
        float f[8] = {a0.x, a0.y, a0.z, a0.w, a1.x, a1.y, a1.z, a1.w};
        P8 ph, pl;
#pragma unroll
        for (int j = 0; j < 8; ++j) {
            __nv_bfloat16 hb = __float2bfloat16(f[j]);
            ph.b[j] = hb;
            pl.b[j] = __float2bfloat16(f[j] - __bfloat162float(hb));
        }
        *(uint4*)&sAhi[row * SPAD + col] = ph.u;
        *(uint4*)&sAlo[row * SPAD + col] = pl.u;
        *(uint4*)&sBhi[row * SPAD + col] = *(const uint4*)&Bhi[(size_t)row * 128 + col];
        *(uint4*)&sBlo[row * SPAD + col] = *(const uint4*)&Blo[(size_t)row * 128 + col];
    }
    __syncthreads();

    // ---- warp tiles: warp w -> rows (w>>1)*32, cols (w&1)*64 ----
    int w = tid >> 5, lane = tid & 31;
    int mw = (w >> 1) * 32, nw = (w & 1) * 64;
    int gr = lane >> 2;              // 0..7
    int c2 = (lane & 3) * 2;         // 0,2,4,6

    float acc[2][8][4];
#pragma unroll
    for (int i = 0; i < 2; ++i)
#pragma unroll
        for (int j = 0; j < 8; ++j)
#pragma unroll
            for (int q = 0; q < 4; ++q) acc[i][j][q] = 0.f;

#pragma unroll
    for (int ks = 0; ks < 8; ++ks) {
        int k0 = ks * 16;
        uint32_t ah[2][4], al[2][4];
#pragma unroll
        for (int mt = 0; mt < 2; ++mt) {
            int r0 = mw + mt * 16 + gr;
            int r1 = r0 + 8;
            ah[mt][0] = *(const uint32_t*)&sAhi[r0 * SPAD + k0 + c2];
            ah[mt][1] = *(const uint32_t*)&sAhi[r1 * SPAD + k0 + c2];
            ah[mt][2] = *(const uint32_t*)&sAhi[r0 * SPAD + k0 + c2 + 8];
            ah[mt][3] = *(const uint32_t*)&sAhi[r1 * SPAD + k0 + c2 + 8];
            al[mt][0] = *(const uint32_t*)&sAlo[r0 * SPAD + k0 + c2];
            al[mt][1] = *(const uint32_t*)&sAlo[r1 * SPAD + k0 + c2];
            al[mt][2] = *(const uint32_t*)&sAlo[r0 * SPAD + k0 + c2 + 8];
            al[mt][3] = *(const uint32_t*)&sAlo[r1 * SPAD + k0 + c2 + 8];
        }
#pragma unroll
        for (int nt = 0; nt < 8; ++nt) {
            int coln = nw + nt * 8 + gr;         // B^T row = output col
            uint32_t bh[2], bl[2];
            bh[0] = *(const uint32_t*)&sBhi[coln * SPAD + k0 + c2];
            bh[1] = *(const uint32_t*)&sBhi[coln * SPAD + k0 + c2 + 8];
            bl[0] = *(const uint32_t*)&sBlo[coln * SPAD + k0 + c2];
            bl[1] = *(const uint32_t*)&sBlo[coln * SPAD + k0 + c2 + 8];
#pragma unroll
            for (int mt = 0; mt < 2; ++mt) {
                mma16816(acc[mt][nt], ah[mt], bh);
                mma16816(acc[mt][nt], ah[mt], bl);
                mma16816(acc[mt][nt], al[mt], bh);
            }
        }
    }

    // ---- epilogue: write C ----
#pragma unroll
    for (int mt = 0; mt < 2; ++mt) {
        int r0 = m0 + mw + mt * 16 + gr;
        int r1 = r0 + 8;
#pragma unroll
        for (int nt = 0; nt < 8; ++nt) {
            int cc = nw + nt * 8 + c2;
            if (r0 < M)
                *(float2*)&C[(size_t)r0 * 128 + cc] =
                    make_float2(acc[mt][nt][0], acc[mt][nt][1]);
            if (r1 < M)
                *(float2*)&C[(size_t)r1 * 128 + cc] =
                    make_float2(acc[mt][nt][2], acc[mt][nt][3]);
        }
    }
}

// ---------------- attention scores ------------------------------------------
__global__ void attn_k(const float* __restrict__ as_, const float* __restrict__ ad_) {
    int n = blockIdx.x * blockDim.x + threadIdx.x;
    if (n >= NN) return;
    const float* hr = &g_h[(size_t)n * 128];
#pragma unroll
    for (int h = 0; h < HH; ++h) {
        float s1 = 0.f, s2 = 0.f;
#pragma unroll
        for (int c = 0; c < CC; c += 4) {
            float4 hv = *(const float4*)&hr[h * CC + c];
            float4 a1 = *(const float4*)&as_[h * CC + c];
            float4 a2 = *(const float4*)&ad_[h * CC + c];
            s1 += hv.x * a1.x + hv.y * a1.y + hv.z * a1.z + hv.w * a1.w;
            s2 += hv.x * a2.x + hv.y * a2.y + hv.z * a2.z + hv.w * a2.w;
        }
        g_esrc[n * HH + h] = s1;
        g_edst[n * HH + h] = s2;
    }
}

// ---------------- warp-per-node online-softmax aggregation ------------------
__global__ void aggregate_k(const float* __restrict__ bias,
                            const float* __restrict__ skb) {
    int warp = (blockIdx.x * blockDim.x + threadIdx.x) >> 5;
    int lane = threadIdx.x & 31;
    if (warp >= NN) return;
    int n = warp;
    int head = lane >> 3;
    float ed = g_edst[n * HH + head];
    int j0 = g_off[n], j1 = g_off[n + 1];
    float m = -1e30f, z = 0.f;
    float4 acc = make_float4(0.f, 0.f, 0.f, 0.f);
    for (int j = j0; j < j1; ++j) {
        int s = g_srcidx[j];
        float e = g_esrc[s * HH + head] + ed;
        e = (e > 0.f) ? e : 0.2f * e;
        float nm = fmaxf(m, e);
        float sc = __expf(m - nm);
        float w  = __expf(e - nm);
        float4 hv = *(const float4*)&g_h[(size_t)s * 128 + lane * 4];
        acc.x = acc.x * sc + w * hv.x;
        acc.y = acc.y * sc + w * hv.y;
        acc.z = acc.z * sc + w * hv.z;
        acc.w = acc.w * sc + w * hv.w;
        z = z * sc + w;
        m = nm;
    }
    float inv = 1.f / z;
    float4 sk = *(const float4*)&g_sk[(size_t)n * 128 + lane * 4];
    float4 bb = *(const float4*)&bias[lane * 4];
    float4 sb = *(const float4*)&skb[lane * 4];
    float4 o;
    o.x = fmaxf(0.f, acc.x * inv + bb.x + sk.x + sb.x);
    o.y = fmaxf(0.f, acc.y * inv + bb.y + sk.y + sb.y);
    o.z = fmaxf(0.f, acc.z * inv + bb.z + sk.z + sb.z);
    o.w = fmaxf(0.f, acc.w * inv + bb.w + sk.w + sb.w);
    *(float4*)&g_x[(size_t)n * 128 + lane * 4] = o;
}

// ---------------- global max pool --------------------------------------------
__global__ void pool_k(const void* __restrict__ batch) {
    int n = blockIdx.x;
    int t = threadIdx.x;
    int is64 = g_is64;
    int g = fetch_idx(batch, n, is64);
    float v = g_x[(size_t)n * 128 + t];
    atomicMax((int*)&g_pool[g * 128 + t], __float_as_int(v));
}

// ---------------- MLP --------------------------------------------------------
__global__ void mlp1_k(const float* __restrict__ w, const float* __restrict__ b) {
    __shared__ float sp[HC];
    int g = blockIdx.x, t = threadIdx.x;
    if (t < HC) sp[t] = g_pool[g * HC + t];
    __syncthreads();
    float s = b[t];
#pragma unroll 8
    for (int k = 0; k < HC; ++k) s += sp[k] * w[(size_t)k * NHID + t];
    g_hid[(size_t)g * NHID + t] = fmaxf(s, 0.f);
}

__global__ void mlp2_k(const float* __restrict__ w, const float* __restrict__ b,
                       float* __restrict__ out) {
    __shared__ float sp[NHID];
    int g = blockIdx.x, t = threadIdx.x;
    if (t < NHID) sp[t] = g_hid[(size_t)g * NHID + t];
    __syncthreads();
    float s = b[t];
#pragma unroll 8
    for (int k = 0; k < NHID; ++k) s += sp[k] * w[(size_t)k * NOUT + t];
    out[(size_t)g * NOUT + t] = s;
}

// ---------------- launch ------------------------------------------------------
extern "C" void kernel_launch(void* const* d_in, const int* in_sizes, int n_in,
                              void* d_out, int out_size) {
    const float* x     = (const float*)d_in[0];
    const void*  ei    = d_in[1];
    const void*  batch = d_in[2];
    const float* w[3]   = {(const float*)d_in[3],  (const float*)d_in[9],  (const float*)d_in[15]};
    const float* as_[3] = {(const float*)d_in[4],  (const float*)d_in[10], (const float*)d_in[16]};
    const float* ad_[3] = {(const float*)d_in[5],  (const float*)d_in[11], (const float*)d_in[17]};
    const float* b[3]   = {(const float*)d_in[6],  (const float*)d_in[12], (const float*)d_in[18]};
    const float* skw[3] = {(const float*)d_in[7],  (const float*)d_in[13], (const float*)d_in[19]};
    const float* skb[3] = {(const float*)d_in[8],  (const float*)d_in[14], (const float*)d_in[20]};
    const float* m1w = (const float*)d_in[21];
    const float* m1b = (const float*)d_in[22];
    const float* m2w = (const float*)d_in[23];
    const float* m2b = (const float*)d_in[24];
    float* out = (float*)d_out;

    float *ph, *psk, *px;
    cudaGetSymbolAddress((void**)&ph,  g_h);
    cudaGetSymbolAddress((void**)&psk, g_sk);
    cudaGetSymbolAddress((void**)&px,  g_x);
    __nv_bfloat16 *pwh, *pwl;
    cudaGetSymbolAddress((void**)&pwh, g_wthi);
    cudaGetSymbolAddress((void**)&pwl, g_wtlo);

    const int SMEM_GEMM = 4 * 128 * SPAD * (int)sizeof(__nv_bfloat16);  // 139264
    cudaFuncSetAttribute(gemm_mma_k, cudaFuncAttributeMaxDynamicSharedMemorySize,
                         SMEM_GEMM);

    const int SCAN_BLOCKS = (NN + 1023) / 1024;   // 49

    detect_k<<<1, 1>>>((const unsigned*)ei);
    init_k<<<(NN + 255) / 256, 256>>>();
    hist_k<<<(EE + 255) / 256, 256>>>(ei);
    scan1_k<<<SCAN_BLOCKS, 1024>>>();
    scan2_k<<<1, 32>>>(SCAN_BLOCKS);
    scan3_k<<<SCAN_BLOCKS, 1024>>>();
    scatter_k<<<(ETOT + 255) / 256, 256>>>(ei);
    prep_w_k<<<6, 256>>>(w[0], skw[0], w[1], skw[1], w[2], skw[2]);

    dim3 ggrid((NN + 127) / 128, 2);
    for (int L = 0; L < 3; ++L) {
        const float* A = (L == 0) ? x : px;
        gemm_mma_k<<<ggrid, 256, SMEM_GEMM>>>(
            A,
            pwh + (2 * L) * 16384,     pwl + (2 * L) * 16384,
            pwh + (2 * L + 1) * 16384, pwl + (2 * L + 1) * 16384,
            ph, psk, NN);
        attn_k<<<(NN + 127) / 128, 128>>>(as_[L], ad_[L]);
        aggregate_k<<<(NN * 32 + 255) / 256, 256>>>(b[L], skb[L]);
    }

    pool_k<<<NN, 128>>>(batch);
    mlp1_k<<<GG, NHID>>>(m1w, m1b);
    mlp2_k<<<GG, NOUT>>>(m2w, m2b, out);
}